// round 10
// baseline (speedup 1.0000x reference)
#include <cuda_runtime.h>
#include <cstdint>

#define BSZ 32
#define CCH 256
#define NPX 4096
#define REGF 0.01f

#define RST 520                    // row stride (floats); 520 % 32 == 8
#define SMEM_FLOATS (64 * RST)     // 33,280 floats = 133,120 B

// ---------------------------------------------------------------------------
// Kernel 1: mean over batch. x: [B, C, N], mean: [C, N]. float4 vectorized.
// ---------------------------------------------------------------------------
__global__ void mvg_mean_kernel(const float* __restrict__ x,
                                float* __restrict__ mean) {
    int idx = blockIdx.x * blockDim.x + threadIdx.x;
    const float4* x4 = (const float4*)x;
    float4 s = make_float4(0.f, 0.f, 0.f, 0.f);
    const int stride = CCH * NPX / 4;
#pragma unroll
    for (int b = 0; b < BSZ; b++) {
        float4 v = x4[b * stride + idx];
        s.x += v.x; s.y += v.y; s.z += v.z; s.w += v.w;
    }
    const float inv = 1.0f / BSZ;
    s.x *= inv; s.y *= inv; s.z *= inv; s.w *= inv;
    ((float4*)mean)[idx] = s;
}

// ---------------------------------------------------------------------------
// tf32 mma.sync m16n8k8 (verified fragment mapping from round-5 kernel).
// ---------------------------------------------------------------------------
__device__ __forceinline__ void mma_tf32(float* d, const unsigned* a,
                                         const unsigned* b) {
    asm volatile(
        "mma.sync.aligned.m16n8k8.row.col.f32.tf32.tf32.f32 "
        "{%0,%1,%2,%3}, {%4,%5,%6,%7}, {%8,%9}, {%0,%1,%2,%3};"
        : "+f"(d[0]), "+f"(d[1]), "+f"(d[2]), "+f"(d[3])
        : "r"(a[0]), "r"(a[1]), "r"(a[2]), "r"(a[3]),
          "r"(b[0]), "r"(b[1]));
}

// ---------------------------------------------------------------------------
// Kernel 2: cov[c,d,n] = (sum_b x_c x_d - B m_c m_d)/(B-1) + REG*(c==d)
// Block = 32c x 32d tile pair (upper-tri of 36, mirrored) x 32 n.
// smem layout: element (row 0..63, n 0..31, b 0..7) stored as (hi,lo) float2:
//   addr = row*520 + n*16 + ((b ^ (n>>2)) << 1)
// RST=520 (== 8 mod 32) + b-XOR swizzle => frag LDS.64 and staging STS.64
// are phase-conflict-free. hi = tf32-truncated raw x, lo = x - hi.
// Products hh + hl + lh accumulated in fp32 (m16n8k8 tf32). 8 warps, each
// owns 4 consecutive n and the full 32x32 (c,d) tile for them.
// Single buffer; LDG prefetch of next chunk held in regs during compute.
// ---------------------------------------------------------------------------
__global__ __launch_bounds__(256, 1)
void mvg_cov_kernel(const float* __restrict__ x,
                    const float* __restrict__ mean,
                    float* __restrict__ cov) {
    // upper-triangular tile pair (ti <= tj) from blockIdx.x in [0,36)
    int rem = blockIdx.x;
    int ti = 0, row8 = 8;
    while (rem >= row8) { rem -= row8; row8--; ti++; }
    const int tj = ti + rem;
    const int n0 = blockIdx.y * 32;

    extern __shared__ float sm[];

    const int tid  = threadIdx.x;
    const int w    = tid >> 5;          // warp: owns n = n0 + 4w .. +3
    const int lane = tid & 31;
    const int g    = lane >> 2;         // fragment groupID
    const int t    = lane & 3;          // fragment threadID-in-group

    // staging coords (chosen for STS.64 phase-conflict-freedom)
    const int s_rowq = tid & 3;
    const int s_nq   = (tid >> 2) & 7;

    // ---- LDG prefetch: 16 float4 per thread per chunk ----
    float4 pf[16];
    auto ldg = [&](int ck) {
        const int kb = ck * 8;
#pragma unroll
        for (int p = 0; p < 16; p++) {
            const int b  = p >> 1;
            const int rh = p & 1;
            const int row = rh * 32 + w * 4 + s_rowq;
            const int src = (row < 32) ? (ti * 32 + row) : (tj * 32 + row - 32);
            pf[p] = *(const float4*)
                &x[((size_t)(kb + b) * CCH + src) * NPX + n0 + s_nq * 4];
        }
    };
    // ---- split + store: (hi,lo) float2 per element ----
    auto sts = [&]() {
#pragma unroll
        for (int p = 0; p < 16; p++) {
            const int b  = p >> 1;
            const int rh = p & 1;
            const int row = rh * 32 + w * 4 + s_rowq;
            float* base = sm + row * RST + s_nq * 64 + ((b ^ s_nq) << 1);
            float v[4] = { pf[p].x, pf[p].y, pf[p].z, pf[p].w };
#pragma unroll
            for (int k = 0; k < 4; k++) {
                float hv = __uint_as_float(__float_as_uint(v[k]) & 0xFFFFE000u);
                float lv = v[k] - hv;
                *(float2*)(base + k * 16) = make_float2(hv, lv);
            }
        }
    };

    // accumulators [cb][db][nn][frag]
    float acc[2][4][4][4];
#pragma unroll
    for (int i = 0; i < 2; i++)
#pragma unroll
        for (int j = 0; j < 4; j++)
#pragma unroll
            for (int k = 0; k < 4; k++)
#pragma unroll
                for (int f = 0; f < 4; f++) acc[i][j][k][f] = 0.f;

    auto compute = [&]() {
#pragma unroll
        for (int nn = 0; nn < 4; nn++) {
            const int n = w * 4 + nn;           // n>>2 == w
            const float* nbase = sm + n * 16;
            unsigned Ah[2][4], Al[2][4];
#pragma unroll
            for (int cb = 0; cb < 2; cb++) {
#pragma unroll
                for (int q = 0; q < 4; q++) {
                    // frag order: (g,t), (g+8,t), (g,t+4), (g+8,t+4)
                    const int rr = cb * 16 + g + (q & 1) * 8;
                    const int bb = t + (q >> 1) * 4;
                    uint2 hl = *(const uint2*)(nbase + rr * RST + ((bb ^ w) << 1));
                    Ah[cb][q] = hl.x; Al[cb][q] = hl.y;
                }
            }
#pragma unroll
            for (int db = 0; db < 4; db++) {
                unsigned Bh[2], Bl[2];
#pragma unroll
                for (int q = 0; q < 2; q++) {
                    const int rr = 32 + db * 8 + g;
                    const int bb = t + q * 4;
                    uint2 hl = *(const uint2*)(nbase + rr * RST + ((bb ^ w) << 1));
                    Bh[q] = hl.x; Bl[q] = hl.y;
                }
#pragma unroll
                for (int cb = 0; cb < 2; cb++) {
                    float* dd = acc[cb][db][nn];
                    mma_tf32(dd, Ah[cb], Bh);   // hi*hi
                    mma_tf32(dd, Ah[cb], Bl);   // hi*lo
                    mma_tf32(dd, Al[cb], Bh);   // lo*hi
                }
            }
        }
    };

    // ---- pipeline: prologue stage, then compute with reg-prefetch ----
    ldg(0); sts();
    __syncthreads();
#pragma unroll
    for (int ck = 0; ck < 4; ck++) {
        if (ck < 3) ldg(ck + 1);     // in flight during compute
        compute();
        __syncthreads();             // all reads of buffer done
        if (ck < 3) {
            sts();
            __syncthreads();         // buffer refilled
        }
    }

    // ---- epilogue: mean correction, scale, reg, float4 writes + mirror ----
    const float scale = 1.0f / (BSZ - 1);
    const int gn = n0 + w * 4;       // 16B aligned
    float4 md[4][2];
#pragma unroll
    for (int db = 0; db < 4; db++)
#pragma unroll
        for (int di = 0; di < 2; di++) {
            const int d = tj * 32 + db * 8 + 2 * t + di;
            md[db][di] = *(const float4*)&mean[(size_t)d * NPX + gn];
        }
#pragma unroll
    for (int cb = 0; cb < 2; cb++) {
#pragma unroll
        for (int ci = 0; ci < 2; ci++) {
            const int c = ti * 32 + cb * 16 + g + ci * 8;
            float4 mc = *(const float4*)&mean[(size_t)c * NPX + gn];
#pragma unroll
            for (int db = 0; db < 4; db++) {
#pragma unroll
                for (int di = 0; di < 2; di++) {
                    const int d = tj * 32 + db * 8 + 2 * t + di;
                    const int fi = ci * 2 + di;
                    float4 o;
                    o.x = (acc[cb][db][0][fi] - (float)BSZ * mc.x * md[db][di].x) * scale;
                    o.y = (acc[cb][db][1][fi] - (float)BSZ * mc.y * md[db][di].y) * scale;
                    o.z = (acc[cb][db][2][fi] - (float)BSZ * mc.z * md[db][di].z) * scale;
                    o.w = (acc[cb][db][3][fi] - (float)BSZ * mc.w * md[db][di].w) * scale;
                    if (c == d) { o.x += REGF; o.y += REGF; o.z += REGF; o.w += REGF; }
                    __stcs((float4*)&cov[((size_t)c * CCH + d) * NPX + gn], o);
                    __stcs((float4*)&cov[((size_t)d * CCH + c) * NPX + gn], o);
                }
            }
        }
    }
}

// ---------------------------------------------------------------------------
extern "C" void kernel_launch(void* const* d_in, const int* in_sizes, int n_in,
                              void* d_out, int out_size) {
    const float* x = (const float*)d_in[0];
    float* out  = (float*)d_out;
    float* mean = out;                          // [C, N]
    float* cov  = out + (size_t)CCH * NPX;      // [C, C, N]

    mvg_mean_kernel<<<(CCH * NPX / 4) / 256, 256>>>(x, mean);

    static bool attr_set = false;
    const int smem_bytes = SMEM_FLOATS * 4;     // 133,120 B
    if (!attr_set) {
        cudaFuncSetAttribute(mvg_cov_kernel,
                             cudaFuncAttributeMaxDynamicSharedMemorySize,
                             smem_bytes);
        attr_set = true;
    }
    dim3 grid(36, NPX / 32);                    // (36, 128)
    mvg_cov_kernel<<<grid, 256, smem_bytes>>>(x, mean, cov);
}

// round 11
// speedup vs baseline: 1.6694x; 1.6694x over previous
#include <cuda_runtime.h>
#include <cstdint>

#define BSZ 32
#define CCH 256
#define NPX 4096
#define REGF 0.01f

#define TNN 64                      // n per block
#define KB  4                       // b per chunk
#define NCHUNK (BSZ / KB)           // 8
#define ROWS 48                     // 32 c-rows + 16 d-rows
#define BUFSZ (ROWS * KB * TNN)     // 12288 floats (48 KB)
#define NBUF 4                      // 192 KB total

typedef unsigned long long ull;

// packed fp32x2 FMA (2 FMAs/instr); ptxas never emits from C++.
__device__ __forceinline__ void ffma2(ull& acc, ull a, ull b) {
    asm("fma.rn.f32x2 %0, %1, %2, %0;" : "+l"(acc) : "l"(a), "l"(b));
}
__device__ __forceinline__ unsigned smem_u32(const void* p) {
    return (unsigned)__cvta_generic_to_shared(p);
}
__device__ __forceinline__ void cp16(unsigned s, const float* g) {
    asm volatile("cp.async.cg.shared.global [%0], [%1], 16;" :: "r"(s), "l"(g));
}
#define CP_COMMIT() asm volatile("cp.async.commit_group;" ::: "memory")
#define CP_WAIT2()  asm volatile("cp.async.wait_group 2;" ::: "memory")

// ---------------------------------------------------------------------------
// Kernel 1: mean over batch. x: [B, C, N], mean: [C, N].
// ---------------------------------------------------------------------------
__global__ void mvg_mean_kernel(const float* __restrict__ x,
                                float* __restrict__ mean) {
    int idx = blockIdx.x * blockDim.x + threadIdx.x;
    const float4* x4 = (const float4*)x;
    float4 s = make_float4(0.f, 0.f, 0.f, 0.f);
    const int stride = CCH * NPX / 4;
#pragma unroll
    for (int b = 0; b < BSZ; b++) {
        float4 v = x4[b * stride + idx];
        s.x += v.x; s.y += v.y; s.z += v.z; s.w += v.w;
    }
    const float inv = 1.0f / BSZ;
    s.x *= inv; s.y *= inv; s.z *= inv; s.w *= inv;
    ((float4*)mean)[idx] = s;
}

// ---------------------------------------------------------------------------
// Kernel 2: cov[c,d,n] = (sum_b x_c x_d - B m_c m_d)/(B-1) + REG*(c==d)
// Block = 32c x 16d x 64n. (ci, dj) with dj >= 2*ci (72 blocks); mirrored
// writes fill the lower triangle. 256 threads = 8 warps; warp w owns
// microtile (tc = w&3, td = w>>2): 8c x 8d x 64n, lane = n-pair.
// (tc,td) is WARP-UNIFORM => for "sub" blocks (d-rows inside c-rows) the
// warps whose microtile lies strictly below the diagonal skip all compute
// (recovers the diagonal-tile FLOP waste: -8.3% FFMA2 vs champion).
// smem layout: buf[(row*KB + b)*TNN + n]; all LDS/STS contiguous 256B.
// Staging: cp.async, 4 buffers, 3 chunks ahead, one sync per chunk.
// ---------------------------------------------------------------------------
__global__ __launch_bounds__(256, 1)
void mvg_cov_kernel(const float* __restrict__ x,
                    const float* __restrict__ mean,
                    float* __restrict__ cov) {
    // decode (ci, dj): ci in [0,8), dj in [2*ci, 16)
    int rem = blockIdx.x;
    int ci = 0;
    while (rem >= 16 - 2 * ci) { rem -= 16 - 2 * ci; ci++; }
    const int dj = 2 * ci + rem;
    const bool sub = (dj >> 1) == ci;        // d-rows subset of c-rows
    const int n0 = blockIdx.y * TNN;

    extern __shared__ float sm[];

    const int tid  = threadIdx.x;
    const int lane = tid & 31;               // n-pair (2 n per thread)
    const int w    = tid >> 5;
    const int tc   = w & 3;                  // 8 c-rows
    const int td   = w >> 2;                 // 8 d-rows
    // skip: whole microtile strictly below diagonal (sub blocks only)
    const bool skipw = sub && ((dj & 1) * 2 + td + 1 <= tc);

    // ---- stage chunk ck into buffer ck % NBUF ----
    const int nstage = sub ? 8 : 12;         // float4s per thread
    auto stage = [&](int ck) {
        float* dst = sm + (ck & (NBUF - 1)) * BUFSZ;
        const int kb = ck * KB;
        for (int r = 0; r < nstage; r++) {
            int f   = r * 256 + tid;         // < 3072 (2048 if sub)
            int n4  = f & 15;
            int b   = (f >> 4) & 3;
            int row = f >> 6;                // 0..47
            int src = (row < 32) ? (ci * 32 + row) : (dj * 16 + row - 32);
            cp16(smem_u32(dst + (row * KB + b) * TNN + n4 * 4),
                 &x[((size_t)(kb + b) * CCH + src) * NPX + n0 + n4 * 4]);
        }
        CP_COMMIT();
    };

    ull acc[8][8];
#pragma unroll
    for (int i = 0; i < 8; i++)
#pragma unroll
        for (int j = 0; j < 8; j++) acc[i][j] = 0ull;

    const int drow0 = sub ? (dj & 1) * 16 : 32;   // d rows base in buffer

    auto compute = [&](int ck) {
        const float* buf = sm + (ck & (NBUF - 1)) * BUFSZ;
        const float* pa = buf + (tc * 8) * (KB * TNN) + 2 * lane;
        const float* pb = buf + (drow0 + td * 8) * (KB * TNN) + 2 * lane;
#pragma unroll
        for (int bb = 0; bb < KB; bb++) {
            ull av[8], bv[8];
#pragma unroll
            for (int i = 0; i < 8; i++)
                av[i] = *(const ull*)&pa[i * (KB * TNN) + bb * TNN];
#pragma unroll
            for (int j = 0; j < 8; j++)
                bv[j] = *(const ull*)&pb[j * (KB * TNN) + bb * TNN];
#pragma unroll
            for (int i = 0; i < 8; i++)
#pragma unroll
                for (int j = 0; j < 8; j++)
                    ffma2(acc[i][j], av[i], bv[j]);
        }
    };

    // ---- pipeline: 4 buffers, 3 chunks in flight, one sync per chunk ----
    stage(0); stage(1); stage(2);
#pragma unroll
    for (int ck = 0; ck < NCHUNK; ck++) {
        CP_WAIT2();                  // group ck complete (ck+3 issued)
        __syncthreads();
        if (!skipw) compute(ck);
        if (ck + 3 < NCHUNK) stage(ck + 3);
        else CP_COMMIT();            // empty group keeps wait count aligned
    }

    if (skipw) return;               // no more syncs below

    // ---- epilogue: mean correction, scale, reg, write + mirror ----
    const float scale = 1.0f / (BSZ - 1);
    const int n = n0 + 2 * lane;
    float2 md[8];
#pragma unroll
    for (int j = 0; j < 8; j++)
        md[j] = *(const float2*)&mean[(size_t)(dj * 16 + td * 8 + j) * NPX + n];
#pragma unroll
    for (int i = 0; i < 8; i++) {
        const int c = ci * 32 + tc * 8 + i;
        float2 mc = *(const float2*)&mean[(size_t)c * NPX + n];
#pragma unroll
        for (int j = 0; j < 8; j++) {
            const int d = dj * 16 + td * 8 + j;
            ull a = acc[i][j];
            float lo = __uint_as_float((unsigned)(a & 0xffffffffull));
            float hi = __uint_as_float((unsigned)(a >> 32));
            lo = (lo - (float)BSZ * mc.x * md[j].x) * scale;
            hi = (hi - (float)BSZ * mc.y * md[j].y) * scale;
            if (c == d) { lo += REGF; hi += REGF; }
            float2 o = make_float2(lo, hi);
            __stcs((float2*)&cov[((size_t)c * CCH + d) * NPX + n], o);
            __stcs((float2*)&cov[((size_t)d * CCH + c) * NPX + n], o);
        }
    }
}

// ---------------------------------------------------------------------------
extern "C" void kernel_launch(void* const* d_in, const int* in_sizes, int n_in,
                              void* d_out, int out_size) {
    const float* x = (const float*)d_in[0];
    float* out  = (float*)d_out;
    float* mean = out;                          // [C, N]
    float* cov  = out + (size_t)CCH * NPX;      // [C, C, N]

    mvg_mean_kernel<<<(CCH * NPX / 4) / 256, 256>>>(x, mean);

    static bool attr_set = false;
    const int smem_bytes = NBUF * BUFSZ * 4;    // 196,608 B
    if (!attr_set) {
        cudaFuncSetAttribute(mvg_cov_kernel,
                             cudaFuncAttributeMaxDynamicSharedMemorySize,
                             smem_bytes);
        attr_set = true;
    }
    dim3 grid(72, NPX / TNN);                   // (72, 64)
    mvg_cov_kernel<<<grid, 256, smem_bytes>>>(x, mean, cov);
}

// round 12
// speedup vs baseline: 1.8789x; 1.1255x over previous
#include <cuda_runtime.h>
#include <cstdint>

#define BSZ 32
#define CCH 256
#define NPX 4096
#define REGF 0.01f

#define TNN 64                      // n per block
#define KB  4                       // b per chunk
#define NCHUNK (BSZ / KB)           // 8
#define ROWS 48                     // 32 c-rows + 16 d-rows
#define BUFSZ (ROWS * KB * TNN)     // 12288 floats (48 KB)
#define NBUF 4                      // 192 KB total

typedef unsigned long long ull;

// packed fp32x2 FMA (2 FMAs/instr); ptxas never emits from C++.
__device__ __forceinline__ void ffma2(ull& acc, ull a, ull b) {
    asm("fma.rn.f32x2 %0, %1, %2, %0;" : "+l"(acc) : "l"(a), "l"(b));
}
__device__ __forceinline__ unsigned smem_u32(const void* p) {
    return (unsigned)__cvta_generic_to_shared(p);
}
__device__ __forceinline__ void cp16(unsigned s, const float* g) {
    asm volatile("cp.async.cg.shared.global [%0], [%1], 16;" :: "r"(s), "l"(g));
}
#define CP_COMMIT() asm volatile("cp.async.commit_group;" ::: "memory")
#define CP_WAIT2()  asm volatile("cp.async.wait_group 2;" ::: "memory")

// ---------------------------------------------------------------------------
// Kernel 1: mean over batch. x: [B, C, N], mean: [C, N].
// ---------------------------------------------------------------------------
__global__ void mvg_mean_kernel(const float* __restrict__ x,
                                float* __restrict__ mean) {
    int idx = blockIdx.x * blockDim.x + threadIdx.x;
    const float4* x4 = (const float4*)x;
    float4 s = make_float4(0.f, 0.f, 0.f, 0.f);
    const int stride = CCH * NPX / 4;
#pragma unroll
    for (int b = 0; b < BSZ; b++) {
        float4 v = x4[b * stride + idx];
        s.x += v.x; s.y += v.y; s.z += v.z; s.w += v.w;
    }
    const float inv = 1.0f / BSZ;
    s.x *= inv; s.y *= inv; s.z *= inv; s.w *= inv;
    ((float4*)mean)[idx] = s;
}

// ---------------------------------------------------------------------------
// Kernel 2: cov[c,d,n] = (sum_b x_c x_d - B m_c m_d)/(B-1) + REG*(c==d)
// Block = 32c x 16d x 64n. (ci, dj) with dj >= 2*ci (72 blocks); mirrored
// writes fill the lower triangle. 8 warps; warp w owns microtile
// (tc = w&3, td = w>>2): 8c x 8d x 64n, lane = n-pair. (tc,td) is
// warp-uniform => sub-block warps strictly below the diagonal skip all
// compute (-8.3% FFMA2). Staging fully unrolled with r-invariant index
// fields (n4, b, r0 constant per thread; row = r0 + 4r) -> minimal ALU.
// cp.async: 4 buffers, 3 chunks ahead, one sync per chunk.
// ---------------------------------------------------------------------------
__global__ __launch_bounds__(256, 1)
void mvg_cov_kernel(const float* __restrict__ x,
                    const float* __restrict__ mean,
                    float* __restrict__ cov) {
    // decode (ci, dj): ci in [0,8), dj in [2*ci, 16)
    int rem = blockIdx.x;
    int ci = 0;
    while (rem >= 16 - 2 * ci) { rem -= 16 - 2 * ci; ci++; }
    const int dj = 2 * ci + rem;
    const bool sub = (dj >> 1) == ci;        // d-rows subset of c-rows
    const int n0 = blockIdx.y * TNN;

    extern __shared__ float sm[];

    const int tid  = threadIdx.x;
    const int lane = tid & 31;               // n-pair (2 n per thread)
    const int w    = tid >> 5;
    const int tc   = w & 3;                  // 8 c-rows
    const int td   = w >> 2;                 // 8 d-rows
    // skip: whole microtile strictly below diagonal (sub blocks only)
    const bool skipw = sub && ((dj & 1) * 2 + td + 1 <= tc);

    // r-invariant staging fields
    const int n4 = tid & 15;                 // float4 column
    const int sb = (tid >> 4) & 3;           // batch-within-chunk
    const int r0 = tid >> 6;                 // base row (0..3)

    // per-thread base pointers (row advances by 4 per unrolled step)
    const float* gc_base = x + ((size_t)sb * CCH + ci * 32 + r0) * NPX + n0 + n4 * 4;
    const float* gd_base = x + ((size_t)sb * CCH + dj * 16 + r0) * NPX + n0 + n4 * 4;
    const unsigned sm_off = (unsigned)(((r0 * KB + sb) * TNN + n4 * 4) * 4);

    // ---- stage chunk ck into buffer ck % NBUF (fully unrolled) ----
    auto stage = [&](int ck) {
        const unsigned dst = smem_u32(sm) + (unsigned)((ck & (NBUF - 1)) * BUFSZ * 4) + sm_off;
        const size_t gofs = (size_t)(ck * KB) * CCH * NPX;
        const float* gc = gc_base + gofs;
#pragma unroll
        for (int r = 0; r < 8; r++)          // c-part rows r0 + 4r (0..31)
            cp16(dst + (unsigned)(r * 4 * KB * TNN * 4), gc + (size_t)r * 4 * NPX);
        if (!sub) {
            const float* gd = gd_base + gofs;
            const unsigned ddst = dst + (unsigned)(32 * KB * TNN * 4);
#pragma unroll
            for (int r = 0; r < 4; r++)      // d-part rows r0 + 4r (0..15)
                cp16(ddst + (unsigned)(r * 4 * KB * TNN * 4), gd + (size_t)r * 4 * NPX);
        }
        CP_COMMIT();
    };

    ull acc[8][8];
#pragma unroll
    for (int i = 0; i < 8; i++)
#pragma unroll
        for (int j = 0; j < 8; j++) acc[i][j] = 0ull;

    const int drow0 = sub ? (dj & 1) * 16 : 32;   // d rows base in buffer

    auto compute = [&](int ck) {
        const float* buf = sm + (ck & (NBUF - 1)) * BUFSZ;
        const float* pa = buf + (tc * 8) * (KB * TNN) + 2 * lane;
        const float* pb = buf + (drow0 + td * 8) * (KB * TNN) + 2 * lane;
#pragma unroll
        for (int bb = 0; bb < KB; bb++) {
            ull av[8], bv[8];
#pragma unroll
            for (int i = 0; i < 8; i++)
                av[i] = *(const ull*)&pa[i * (KB * TNN) + bb * TNN];
#pragma unroll
            for (int j = 0; j < 8; j++)
                bv[j] = *(const ull*)&pb[j * (KB * TNN) + bb * TNN];
#pragma unroll
            for (int i = 0; i < 8; i++)
#pragma unroll
                for (int j = 0; j < 8; j++)
                    ffma2(acc[i][j], av[i], bv[j]);
        }
    };

    // ---- pipeline: 4 buffers, 3 chunks in flight, one sync per chunk ----
    stage(0); stage(1); stage(2);
#pragma unroll
    for (int ck = 0; ck < NCHUNK; ck++) {
        CP_WAIT2();                  // group ck complete (ck+3 issued)
        __syncthreads();
        if (!skipw) compute(ck);
        if (ck + 3 < NCHUNK) stage(ck + 3);
        else CP_COMMIT();            // empty group keeps wait count aligned
    }

    if (skipw) return;               // no more syncs below

    // ---- epilogue: mean correction, scale, reg, write + mirror ----
    const float scale = 1.0f / (BSZ - 1);
    const int n = n0 + 2 * lane;
    float2 md[8];
#pragma unroll
    for (int j = 0; j < 8; j++)
        md[j] = *(const float2*)&mean[(size_t)(dj * 16 + td * 8 + j) * NPX + n];
#pragma unroll
    for (int i = 0; i < 8; i++) {
        const int c = ci * 32 + tc * 8 + i;
        float2 mc = *(const float2*)&mean[(size_t)c * NPX + n];
#pragma unroll
        for (int j = 0; j < 8; j++) {
            const int d = dj * 16 + td * 8 + j;
            ull a = acc[i][j];
            float lo = __uint_as_float((unsigned)(a & 0xffffffffull));
            float hi = __uint_as_float((unsigned)(a >> 32));
            lo = (lo - (float)BSZ * mc.x * md[j].x) * scale;
            hi = (hi - (float)BSZ * mc.y * md[j].y) * scale;
            if (c == d) { lo += REGF; hi += REGF; }
            float2 o = make_float2(lo, hi);
            __stcs((float2*)&cov[((size_t)c * CCH + d) * NPX + n], o);
            __stcs((float2*)&cov[((size_t)d * CCH + c) * NPX + n], o);
        }
    }
}

// ---------------------------------------------------------------------------
extern "C" void kernel_launch(void* const* d_in, const int* in_sizes, int n_in,
                              void* d_out, int out_size) {
    const float* x = (const float*)d_in[0];
    float* out  = (float*)d_out;
    float* mean = out;                          // [C, N]
    float* cov  = out + (size_t)CCH * NPX;      // [C, C, N]

    mvg_mean_kernel<<<(CCH * NPX / 4) / 256, 256>>>(x, mean);

    static bool attr_set = false;
    const int smem_bytes = NBUF * BUFSZ * 4;    // 196,608 B
    if (!attr_set) {
        cudaFuncSetAttribute(mvg_cov_kernel,
                             cudaFuncAttributeMaxDynamicSharedMemorySize,
                             smem_bytes);
        attr_set = true;
    }
    dim3 grid(72, NPX / TNN);                   // (72, 64)
    mvg_cov_kernel<<<grid, 256, smem_bytes>>>(x, mean, cov);
}

// round 13
// speedup vs baseline: 1.9259x; 1.0250x over previous
#include <cuda_runtime.h>
#include <cstdint>

#define BSZ 32
#define CCH 256
#define NPX 4096
#define REGF 0.01f

#define TN  32                      // n per block
#define KB  4                       // b per chunk
#define NCHUNK (BSZ / KB)           // 8
#define BUFSZ (64 * KB * TN)        // 8192 floats (32 KB): 64 rows x 4 b x 32 n
#define NBUF 4                      // 128 KB total

typedef unsigned long long ull;

// packed fp32x2 FMA (2 FMAs/instr); ptxas never emits from C++.
__device__ __forceinline__ void ffma2(ull& acc, ull a, ull b) {
    asm("fma.rn.f32x2 %0, %1, %2, %0;" : "+l"(acc) : "l"(a), "l"(b));
}
__device__ __forceinline__ unsigned smem_u32(const void* p) {
    return (unsigned)__cvta_generic_to_shared(p);
}
__device__ __forceinline__ void cp16(unsigned s, const float* g) {
    asm volatile("cp.async.cg.shared.global [%0], [%1], 16;" :: "r"(s), "l"(g));
}
#define CP_COMMIT() asm volatile("cp.async.commit_group;" ::: "memory")
#define CP_WAIT2()  asm volatile("cp.async.wait_group 2;" ::: "memory")

// ---------------------------------------------------------------------------
// Kernel 1: mean over batch. x: [B, C, N], mean: [C, N].
// ---------------------------------------------------------------------------
__global__ void mvg_mean_kernel(const float* __restrict__ x,
                                float* __restrict__ mean) {
    int idx = blockIdx.x * blockDim.x + threadIdx.x;
    const float4* x4 = (const float4*)x;
    float4 s = make_float4(0.f, 0.f, 0.f, 0.f);
    const int stride = CCH * NPX / 4;
#pragma unroll
    for (int b = 0; b < BSZ; b++) {
        float4 v = x4[b * stride + idx];
        s.x += v.x; s.y += v.y; s.z += v.z; s.w += v.w;
    }
    const float inv = 1.0f / BSZ;
    s.x *= inv; s.y *= inv; s.z *= inv; s.w *= inv;
    ((float4*)mean)[idx] = s;
}

// ---------------------------------------------------------------------------
// Kernel 2: cov[c,d,n] = (sum_b x_c x_d - B m_c m_d)/(B-1) + REG*(c==d)
// Champion geometry: block = 32c x 32d tile pair (36 upper-tri pairs,
// mirrored writes) x 32 n. Thread microtile 8c x 8d x 2n, packed f32x2.
// Pipeline: cp.async, 4 buffers, KB=4 chunks, 3 in flight, ONE sync/chunk.
// Staging fully unrolled with r-invariant fields (n4, b, r0 per-thread
// constants; row = r0 + 8r) -> minimal ALU.
// ---------------------------------------------------------------------------
__global__ __launch_bounds__(256, 1)
void mvg_cov_kernel(const float* __restrict__ x,
                    const float* __restrict__ mean,
                    float* __restrict__ cov) {
    // upper-triangular tile pair (ti <= tj) from blockIdx.x in [0,36)
    int rem = blockIdx.x;
    int ti = 0, row8 = 8;
    while (rem >= row8) { rem -= row8; row8--; ti++; }
    const int tj = ti + rem;
    const bool diag = (ti == tj);
    const int n0 = blockIdx.y * TN;

    extern __shared__ float sm[];

    const int tid = threadIdx.x;
    const int tn  = tid & 15;        // n-pair index (2 n per thread)
    const int tcd = tid >> 4;
    const int tc  = tcd & 3;         // 8 c-rows
    const int td  = tcd >> 2;        // 8 d-rows

    // r-invariant staging fields: f = r*256 + tid
    const int n4 = tid & 7;          // float4 column (0..7)
    const int sb = (tid >> 3) & 3;   // batch-within-chunk
    const int r0 = tid >> 5;         // base row (0..7); row = r0 + 8r

    const float* gc_base = x + ((size_t)sb * CCH + ti * 32 + r0) * NPX + n0 + n4 * 4;
    const float* gd_base = x + ((size_t)sb * CCH + tj * 32 + r0) * NPX + n0 + n4 * 4;
    const unsigned sm_off = (unsigned)(((r0 * KB + sb) * TN + n4 * 4) * 4);

    // ---- stage chunk ck into buffer ck % NBUF (fully unrolled) ----
    auto stage = [&](int ck) {
        const unsigned dst = smem_u32(sm)
            + (unsigned)((ck & (NBUF - 1)) * BUFSZ * 4) + sm_off;
        const size_t gofs = (size_t)(ck * KB) * CCH * NPX;
        const float* gc = gc_base + gofs;
#pragma unroll
        for (int r = 0; r < 4; r++)   // c-rows r0 + 8r (0..31)
            cp16(dst + (unsigned)(r * 8 * KB * TN * 4), gc + (size_t)r * 8 * NPX);
        if (!diag) {
            const float* gd = gd_base + gofs;
            const unsigned ddst = dst + (unsigned)(32 * KB * TN * 4);
#pragma unroll
            for (int r = 0; r < 4; r++)  // d-rows
                cp16(ddst + (unsigned)(r * 8 * KB * TN * 4), gd + (size_t)r * 8 * NPX);
        }
        CP_COMMIT();
    };

    ull acc[8][8];
#pragma unroll
    for (int i = 0; i < 8; i++)
#pragma unroll
        for (int j = 0; j < 8; j++) acc[i][j] = 0ull;

    const int drow0 = diag ? 0 : 32;

    auto compute = [&](int ck) {
        const float* buf = sm + (ck & (NBUF - 1)) * BUFSZ;
        const float* pa = buf + (tc * 8) * (KB * TN) + 2 * tn;
        const float* pb = buf + (drow0 + td * 8) * (KB * TN) + 2 * tn;
#pragma unroll
        for (int bb = 0; bb < KB; bb++) {
            ull av[8], bv[8];
#pragma unroll
            for (int i = 0; i < 8; i++)
                av[i] = *(const ull*)&pa[i * (KB * TN) + bb * TN];
#pragma unroll
            for (int j = 0; j < 8; j++)
                bv[j] = *(const ull*)&pb[j * (KB * TN) + bb * TN];
#pragma unroll
            for (int i = 0; i < 8; i++)
#pragma unroll
                for (int j = 0; j < 8; j++)
                    ffma2(acc[i][j], av[i], bv[j]);
        }
    };

    // ---- pipeline: 4 buffers, 3 chunks in flight, one sync per chunk ----
    stage(0); stage(1); stage(2);
#pragma unroll
    for (int ck = 0; ck < NCHUNK; ck++) {
        CP_WAIT2();                  // groups 0..ck complete
        __syncthreads();             // data visible; prev compute done
        compute(ck);
        if (ck + 3 < NCHUNK) stage(ck + 3);
        else CP_COMMIT();            // empty group keeps wait count aligned
    }

    // ---- epilogue: mean correction, scale, reg, write + mirror ----
    const float scale = 1.0f / (BSZ - 1);
    const int n = n0 + 2 * tn;
    float2 md[8];
#pragma unroll
    for (int j = 0; j < 8; j++)
        md[j] = *(const float2*)&mean[(size_t)(tj * 32 + td * 8 + j) * NPX + n];
#pragma unroll
    for (int i = 0; i < 8; i++) {
        const int c = ti * 32 + tc * 8 + i;
        float2 mc = *(const float2*)&mean[(size_t)c * NPX + n];
#pragma unroll
        for (int j = 0; j < 8; j++) {
            const int d = tj * 32 + td * 8 + j;
            ull a = acc[i][j];
            float lo = __uint_as_float((unsigned)(a & 0xffffffffull));
            float hi = __uint_as_float((unsigned)(a >> 32));
            lo = (lo - (float)BSZ * mc.x * md[j].x) * scale;
            hi = (hi - (float)BSZ * mc.y * md[j].y) * scale;
            if (c == d) { lo += REGF; hi += REGF; }
            float2 o = make_float2(lo, hi);
            __stcs((float2*)&cov[((size_t)c * CCH + d) * NPX + n], o);
            if (!diag)
                __stcs((float2*)&cov[((size_t)d * CCH + c) * NPX + n], o);
        }
    }
}

// ---------------------------------------------------------------------------
extern "C" void kernel_launch(void* const* d_in, const int* in_sizes, int n_in,
                              void* d_out, int out_size) {
    const float* x = (const float*)d_in[0];
    float* out  = (float*)d_out;
    float* mean = out;                          // [C, N]
    float* cov  = out + (size_t)CCH * NPX;      // [C, C, N]

    mvg_mean_kernel<<<(CCH * NPX / 4) / 256, 256>>>(x, mean);

    static bool attr_set = false;
    const int smem_bytes = NBUF * BUFSZ * 4;    // 131,072 B
    if (!attr_set) {
        cudaFuncSetAttribute(mvg_cov_kernel,
                             cudaFuncAttributeMaxDynamicSharedMemorySize,
                             smem_bytes);
        attr_set = true;
    }
    dim3 grid(36, NPX / TN);                    // (36, 128)
    mvg_cov_kernel<<<grid, 256, smem_bytes>>>(x, mean, cov);
}